// round 5
// baseline (speedup 1.0000x reference)
#include <cuda_runtime.h>
#include <cuda_bf16.h>
#include <cstdint>

// ---------------- problem constants ----------------
#define KSNAP 8
#define NNODE 10000
#define NEDGE 160000
#define EPTOT (NEDGE + NNODE)   // edges + self loops = 170000
#define HEADS 8
#define D2 256
#define LH 256
#define NEG 0.2f
#define NTOT (KSNAP * NNODE)    // 80000

// ---------------- static scratch ----------------
static __device__ unsigned int g_featb[NTOT * 128];    // h_lin bf16x2 packed
static __device__ float g_t   [NTOT * HEADS];          // layer-1 aggregated scalars per head
static __device__ float g_ssrc[NTOT * HEADS];
static __device__ float g_sdst[NTOT * HEADS];
static __device__ float g_q   [2 * HEADS];
static __device__ int   g_deg [KSNAP * NNODE];
static __device__ int   g_off [KSNAP * (NNODE + 1)];
static __device__ int   g_pos [KSNAP * NNODE];
static __device__ int   g_adj [KSNAP * EPTOT];
static __device__ float g_emb [KSNAP * D2];
static __device__ float g_xw  [2 * KSNAP * 4 * LH];
static __device__ float2 g_whhT2[2 * 128 * 1024];

// ---------------- helpers ----------------
__device__ __forceinline__ float warp_sum(float v) {
#pragma unroll
    for (int o = 16; o; o >>= 1) v += __shfl_xor_sync(0xffffffffu, v, o);
    return v;
}
__device__ __forceinline__ float warp_max(float v) {
#pragma unroll
    for (int o = 16; o; o >>= 1) v = fmaxf(v, __shfl_xor_sync(0xffffffffu, v, o));
    return v;
}
__device__ __forceinline__ float warp_min(float v) {
#pragma unroll
    for (int o = 16; o; o >>= 1) v = fminf(v, __shfl_xor_sync(0xffffffffu, v, o));
    return v;
}
#define FMA2(d, a, b) asm("fma.rn.f32x2 %0, %1, %2, %0;" : "+l"(d) : "l"(a), "l"(b))
__device__ __forceinline__ unsigned long long dup2(float a) {
    unsigned long long r;
    asm("mov.b64 %0, {%1, %1};" : "=l"(r) : "r"(__float_as_uint(a)));
    return r;
}
__device__ __forceinline__ void unpack2(unsigned long long v, float& lo, float& hi) {
    lo = __uint_as_float((unsigned int)(v & 0xffffffffull));
    hi = __uint_as_float((unsigned int)(v >> 32));
}
__device__ __forceinline__ float lky(float e) { return (e >= 0.f) ? e : NEG * e; }
__device__ __forceinline__ uint32_t pack_bf16x2(float a, float b) {
    __nv_bfloat162 p = __float22bfloat162_rn(make_float2(a, b));
    return *(uint32_t*)&p;
}

// ---------------- CSR build ----------------
__global__ void k_zero() {
    int i = blockIdx.x * blockDim.x + threadIdx.x;
    if (i < KSNAP * NNODE) g_deg[i] = 0;
    if (i < KSNAP * D2)    g_emb[i] = 0.f;
}

__global__ void k_count(const int* __restrict__ ei) {
    int idx = blockIdx.x * blockDim.x + threadIdx.x;
    if (idx >= KSNAP * EPTOT) return;
    int k = idx / EPTOT, e = idx % EPTOT;
    int dst = (e < NEDGE) ? ei[(k * 2 + 1) * NEDGE + e] : (e - NEDGE);
    atomicAdd(&g_deg[k * NNODE + dst], 1);
}

__global__ void k_scan() {
    __shared__ int part[1024];
    int k = blockIdx.x, t = threadIdx.x;
    int base = t * 10;
    int loc[10];
    int s = 0;
#pragma unroll
    for (int i = 0; i < 10; i++) {
        int n = base + i;
        int v = (n < NNODE) ? g_deg[k * NNODE + n] : 0;
        loc[i] = s; s += v;
    }
    part[t] = s;
    __syncthreads();
    for (int ofs = 1; ofs < 1024; ofs <<= 1) {
        int v = (t >= ofs) ? part[t - ofs] : 0;
        __syncthreads();
        part[t] += v;
        __syncthreads();
    }
    int pre = (t == 0) ? 0 : part[t - 1];
#pragma unroll
    for (int i = 0; i < 10; i++) {
        int n = base + i;
        if (n < NNODE) {
            int o = pre + loc[i];
            g_off[k * (NNODE + 1) + n] = o;
            g_pos[k * NNODE + n]       = o;
        }
    }
    if (t == 1023) g_off[k * (NNODE + 1) + NNODE] = part[1023];
}

__global__ void k_scatter(const int* __restrict__ ei) {
    int idx = blockIdx.x * blockDim.x + threadIdx.x;
    if (idx >= KSNAP * EPTOT) return;
    int k = idx / EPTOT, e = idx % EPTOT;
    int src, dst;
    if (e < NEDGE) {
        src = ei[(k * 2 + 0) * NEDGE + e];
        dst = ei[(k * 2 + 1) * NEDGE + e];
    } else {
        src = e - NEDGE;
        dst = e - NEDGE;
    }
    int slot = atomicAdd(&g_pos[k * NNODE + dst], 1);
    g_adj[k * EPTOT + slot] = src;
}

// ---------------- prep: q vectors ----------------
__global__ void k_prep(const float* __restrict__ W1, const float* __restrict__ as1,
                       const float* __restrict__ ad1) {
    int c = threadIdx.x;
    float w = W1[c];
    float vs = warp_sum(w * as1[c]);
    float vd = warp_sum(w * ad1[c]);
    if ((c & 31) == 0) {
        g_q[c >> 5] = vs;
        g_q[8 + (c >> 5)] = vd;
    }
}

// ---------------- layer-1 GAT, scalar, exact-max ----------------
__global__ __launch_bounds__(256) void k_agg1(const float* __restrict__ xs) {
    int k = blockIdx.y;
    int n = blockIdx.x * 8 + (threadIdx.x >> 5);
    int lane = threadIdx.x & 31;
    long base = (long)k * NNODE;
    int o0 = g_off[k * (NNODE + 1) + n];
    int o1 = g_off[k * (NNODE + 1) + n + 1];
    const int* adj = g_adj + (long)k * EPTOT;

    float qs[HEADS], dterm[HEADS];
    float xd = xs[base + n];
#pragma unroll
    for (int i = 0; i < HEADS; i++) { qs[i] = g_q[i]; dterm[i] = xd * g_q[8 + i]; }

    // pass 1: min/max of x over sources (exact max via monotonicity of leaky_relu)
    float xmx = -1e30f, xmn = 1e30f;
    for (int j = o0 + lane; j < o1; j += 32) {
        float xv = xs[base + adj[j]];
        xmx = fmaxf(xmx, xv); xmn = fminf(xmn, xv);
    }
    xmx = warp_max(xmx); xmn = warp_min(xmn);
    float m[HEADS];
#pragma unroll
    for (int i = 0; i < HEADS; i++)
        m[i] = lky(fmaf(qs[i], (qs[i] >= 0.f) ? xmx : xmn, dterm[i]));

    // pass 2: fused denominator + weighted sum
    float dsum[HEADS], tt[HEADS];
#pragma unroll
    for (int i = 0; i < HEADS; i++) { dsum[i] = 0.f; tt[i] = 0.f; }
    for (int j = o0 + lane; j < o1; j += 32) {
        float xv = xs[base + adj[j]];
#pragma unroll
        for (int i = 0; i < HEADS; i++) {
            float e = lky(fmaf(xv, qs[i], dterm[i]));
            float ex = __expf(e - m[i]);
            dsum[i] += ex;
            tt[i] = fmaf(ex, xv, tt[i]);
        }
    }
#pragma unroll
    for (int i = 0; i < HEADS; i++) {
        float ds = warp_sum(dsum[i]);
        float ts = warp_sum(tt[i]);
        if (lane == 0) g_t[(base + n) * HEADS + i] = ts / (ds + 1e-16f);
    }
}

// ---------------- FFMA2 GEMM: h_lin = relu(outer(t,W1)+b1) @ W2 ----------------
// A generated in registers (no A smem traffic); B f32 in smem; fp32 exact.
__global__ __launch_bounds__(256, 2) void k_gemm(const float* __restrict__ W2,
                                                 const float* __restrict__ W1,
                                                 const float* __restrict__ b1,
                                                 const float* __restrict__ as2,
                                                 const float* __restrict__ ad2) {
    __shared__ float t_sh[128][8];      // 4KB
    __shared__ float W1s[256], b1s[256];
    __shared__ float sAs[128], sAd[128];
    __shared__ float Bs[32][128];       // 16KB, one 32-k chunk (= one head)
    int tid = threadIdx.x;
    int tx = tid & 15, ty = tid >> 4;
    long m0 = (long)blockIdx.x * 128;
    int n0 = blockIdx.y * 128;

    W1s[tid] = W1[tid];
    b1s[tid] = b1[tid];
    if (tid < 128) { sAs[tid] = as2[n0 + tid]; sAd[tid] = ad2[n0 + tid]; }
    {
        int row = tid >> 1, part = tid & 1;
        *(float4*)&t_sh[row][part * 4] = *(const float4*)&g_t[(m0 + row) * 8 + part * 4];
    }
    __syncthreads();

    unsigned long long acc2[8][4];
#pragma unroll
    for (int r = 0; r < 8; r++)
#pragma unroll
        for (int p = 0; p < 4; p++) acc2[r][p] = 0ull;

    for (int ch = 0; ch < 8; ch++) {    // 8 chunks of 32 k (chunk == head)
        int k0 = ch * 32;
        // fill Bs: 32 rows x 128 cols
#pragma unroll
        for (int q = 0; q < 4; q++) {
            int id = tid + q * 256;
            int row = id >> 5, cq = id & 31;
            *(float4*)&Bs[row][cq * 4] = *(const float4*)&W2[(long)(k0 + row) * D2 + n0 + cq * 4];
        }
        __syncthreads();

        float tr[8];
#pragma unroll
        for (int r = 0; r < 8; r++) tr[r] = t_sh[ty * 8 + r][ch];

#pragma unroll 4
        for (int kk = 0; kk < 32; kk++) {
            float w = W1s[k0 + kk];
            float bb = b1s[k0 + kk];
            unsigned long long av[8];
#pragma unroll
            for (int r = 0; r < 8; r++)
                av[r] = dup2(fmaxf(fmaf(w, tr[r], bb), 0.f));
            ulonglong2 b01 = *(const ulonglong2*)&Bs[kk][tx * 8];
            ulonglong2 b23 = *(const ulonglong2*)&Bs[kk][tx * 8 + 4];
            unsigned long long bv[4] = {b01.x, b01.y, b23.x, b23.y};
#pragma unroll
            for (int r = 0; r < 8; r++)
#pragma unroll
                for (int p = 0; p < 4; p++) FMA2(acc2[r][p], av[r], bv[p]);
        }
        __syncthreads();
    }

    float accf[8][8];
#pragma unroll
    for (int r = 0; r < 8; r++)
#pragma unroll
        for (int p = 0; p < 4; p++) unpack2(acc2[r][p], accf[r][2 * p], accf[r][2 * p + 1]);

    // store features as bf16x2
#pragma unroll
    for (int r = 0; r < 8; r++) {
        long row = m0 + ty * 8 + r;
        uint4 pkd = make_uint4(pack_bf16x2(accf[r][0], accf[r][1]),
                               pack_bf16x2(accf[r][2], accf[r][3]),
                               pack_bf16x2(accf[r][4], accf[r][5]),
                               pack_bf16x2(accf[r][6], accf[r][7]));
        *(uint4*)&g_featb[row * 128 + n0 / 2 + tx * 4] = pkd;
    }

    // s-vectors: 4-lane groups own one head (32 cols)
    float avs[8], avd[8];
#pragma unroll
    for (int q = 0; q < 8; q++) {
        avs[q] = sAs[tx * 8 + q];
        avd[q] = sAd[tx * 8 + q];
    }
    int head = (n0 >> 5) + (tx >> 2);
#pragma unroll
    for (int r = 0; r < 8; r++) {
        float ss = 0.f, sd = 0.f;
#pragma unroll
        for (int q = 0; q < 8; q++) {
            ss = fmaf(accf[r][q], avs[q], ss);
            sd = fmaf(accf[r][q], avd[q], sd);
        }
        ss += __shfl_xor_sync(0xffffffffu, ss, 1);
        ss += __shfl_xor_sync(0xffffffffu, ss, 2);
        sd += __shfl_xor_sync(0xffffffffu, sd, 1);
        sd += __shfl_xor_sync(0xffffffffu, sd, 2);
        if ((tx & 3) == 0) {
            long row = m0 + ty * 8 + r;
            g_ssrc[row * HEADS + head] = ss;
            g_sdst[row * HEADS + head] = sd;
        }
    }
}

// ---------------- layer-2 GAT aggregation + fused mean pool ----------------
__global__ __launch_bounds__(256) void k_agg2(const float* __restrict__ bias) {
    __shared__ float s_m[8][8];
    int k = blockIdx.y;
    int w = threadIdx.x >> 5;
    int n = blockIdx.x * 8 + w;
    int lane = threadIdx.x & 31;
    long base = (long)k * NNODE;
    int o0 = g_off[k * (NNODE + 1) + n];
    int o1 = g_off[k * (NNODE + 1) + n + 1];
    const int* adj = g_adj + (long)k * EPTOT;

    float sd[HEADS];
    {
        float4 d0 = *(const float4*)&g_sdst[(base + n) * HEADS];
        float4 d1 = *(const float4*)&g_sdst[(base + n) * HEADS + 4];
        sd[0] = d0.x; sd[1] = d0.y; sd[2] = d0.z; sd[3] = d0.w;
        sd[4] = d1.x; sd[5] = d1.y; sd[6] = d1.z; sd[7] = d1.w;
    }

    // pass 1: per-head max of ssrc over sources (exact; leaky is monotone)
    float mx[HEADS];
#pragma unroll
    for (int i = 0; i < HEADS; i++) mx[i] = -1e30f;
    for (int j = o0 + lane; j < o1; j += 32) {
        const float4* sp = (const float4*)&g_ssrc[((long)base + adj[j]) * HEADS];
        float4 s0 = sp[0], s1 = sp[1];
        mx[0] = fmaxf(mx[0], s0.x); mx[1] = fmaxf(mx[1], s0.y);
        mx[2] = fmaxf(mx[2], s0.z); mx[3] = fmaxf(mx[3], s0.w);
        mx[4] = fmaxf(mx[4], s1.x); mx[5] = fmaxf(mx[5], s1.y);
        mx[6] = fmaxf(mx[6], s1.z); mx[7] = fmaxf(mx[7], s1.w);
    }
#pragma unroll
    for (int i = 0; i < HEADS; i++) mx[i] = warp_max(mx[i]);
    if (lane == 0) {
#pragma unroll
        for (int i = 0; i < HEADS; i++) s_m[w][i] = lky(mx[i] + sd[i]);
    }
    __syncwarp();

    int hl = lane >> 2;
    float m_l = s_m[w][hl];
    float sd_l = sd[hl];

    // pass 2 (serial per warp): fused denominator + weighted bf16 gather
    float dsum = 0.f;
    float a0 = 0.f, a1 = 0.f, a2 = 0.f, a3 = 0.f, a4 = 0.f, a5 = 0.f, a6 = 0.f, a7 = 0.f;
    for (int j = o0; j < o1; j++) {
        long s = adj[j];
        float e = lky(g_ssrc[(base + s) * HEADS + hl] + sd_l);
        float al = __expf(e - m_l);
        dsum += al;
        uint4 fv = *(const uint4*)&g_featb[(base + s) * 128 + lane * 4];
        float2 f0 = __bfloat1622float2(*(__nv_bfloat162*)&fv.x);
        float2 f1 = __bfloat1622float2(*(__nv_bfloat162*)&fv.y);
        float2 f2 = __bfloat1622float2(*(__nv_bfloat162*)&fv.z);
        float2 f3 = __bfloat1622float2(*(__nv_bfloat162*)&fv.w);
        a0 = fmaf(f0.x, al, a0); a1 = fmaf(f0.y, al, a1);
        a2 = fmaf(f1.x, al, a2); a3 = fmaf(f1.y, al, a3);
        a4 = fmaf(f2.x, al, a4); a5 = fmaf(f2.y, al, a5);
        a6 = fmaf(f3.x, al, a6); a7 = fmaf(f3.y, al, a7);
    }
    float inv = 1.f / (dsum + 1e-16f);
    float4 b0 = *(const float4*)&bias[lane * 8];
    float4 b1v = *(const float4*)&bias[lane * 8 + 4];
    float o0v = fmaxf(fmaf(a0, inv, b0.x), 0.f);
    float o1v = fmaxf(fmaf(a1, inv, b0.y), 0.f);
    float o2v = fmaxf(fmaf(a2, inv, b0.z), 0.f);
    float o3v = fmaxf(fmaf(a3, inv, b0.w), 0.f);
    float o4v = fmaxf(fmaf(a4, inv, b1v.x), 0.f);
    float o5v = fmaxf(fmaf(a5, inv, b1v.y), 0.f);
    float o6v = fmaxf(fmaf(a6, inv, b1v.z), 0.f);
    float o7v = fmaxf(fmaf(a7, inv, b1v.w), 0.f);
    const float s = 1.0f / NNODE;
    float* ep = &g_emb[k * D2 + lane * 8];
    atomicAdd(ep + 0, o0v * s); atomicAdd(ep + 1, o1v * s);
    atomicAdd(ep + 2, o2v * s); atomicAdd(ep + 3, o3v * s);
    atomicAdd(ep + 4, o4v * s); atomicAdd(ep + 5, o5v * s);
    atomicAdd(ep + 6, o6v * s); atomicAdd(ep + 7, o7v * s);
}

// ---------------- LSTM input projections ----------------
__global__ void k_xw(const float* __restrict__ Wih_f, const float* __restrict__ Wih_b) {
    int gid = blockIdx.x * 8 + (threadIdx.x >> 5);
    int lane = threadIdx.x & 31;
    int d = gid >> 13;
    int rem = gid & 8191;
    int k = rem >> 10;
    int g = rem & 1023;
    const float* Wih = d ? Wih_b : Wih_f;
    float s = 0.f;
    for (int j = lane; j < D2; j += 32)
        s += Wih[g * D2 + j] * g_emb[k * D2 + j];
    s = warp_sum(s);
    if (lane == 0) g_xw[gid] = s;
}

__global__ void k_whhT(const float* __restrict__ Whh_f, const float* __restrict__ Whh_b) {
    int idx = blockIdx.x * blockDim.x + threadIdx.x;
    if (idx >= 2 * 128 * 1024) return;
    int d = idx >> 17;
    int r = idx & ((1 << 17) - 1);
    int j2 = r >> 10;
    int t = r & 1023;
    const float* W = d ? Whh_b : Whh_f;
    g_whhT2[(((long)d * 128 + j2) << 10) + t] = make_float2(W[t * 256 + 2 * j2], W[t * 256 + 2 * j2 + 1]);
}

// ---------------- bidirectional LSTM ----------------
__global__ __launch_bounds__(1024) void k_lstm(const float* __restrict__ bih_f, const float* __restrict__ bhh_f,
                                               const float* __restrict__ bih_b, const float* __restrict__ bhh_b,
                                               float* __restrict__ out) {
    int d = blockIdx.x;
    int t = threadIdx.x;
    __shared__ float2 h2[LH / 2];
    __shared__ float cc[LH], gbuf[4 * LH];
    if (t < LH / 2) h2[t] = make_float2(0.f, 0.f);
    if (t < LH) cc[t] = 0.f;
    const float* bih = d ? bih_b : bih_f;
    const float* bhh = d ? bhh_b : bhh_f;
    const unsigned long long* WT = (const unsigned long long*)(g_whhT2 + (long)d * 128 * 1024);
    const unsigned long long* hp = (const unsigned long long*)h2;
    float bsum = bih[t] + bhh[t];
    __syncthreads();
    for (int step = 0; step < KSNAP; step++) {
        int kk = d ? (KSNAP - 1 - step) : step;
        unsigned long long acc2 = 0ull;
#pragma unroll 8
        for (int j2 = 0; j2 < LH / 2; j2++) {
            unsigned long long w = WT[(long)j2 * 1024 + t];
            unsigned long long hh = hp[j2];
            FMA2(acc2, w, hh);
        }
        float lo, hi;
        unpack2(acc2, lo, hi);
        gbuf[t] = lo + hi + g_xw[((long)d * KSNAP + kk) * 1024 + t] + bsum;
        __syncthreads();
        if (t < LH) {
            float ig = 1.f / (1.f + expf(-gbuf[t]));
            float fg = 1.f / (1.f + expf(-gbuf[LH + t]));
            float gg = tanhf(gbuf[2 * LH + t]);
            float og = 1.f / (1.f + expf(-gbuf[3 * LH + t]));
            float cn = fg * cc[t] + ig * gg;
            cc[t] = cn;
            ((float*)h2)[t] = og * tanhf(cn);
        }
        __syncthreads();
    }
    if (t < LH) out[d * LH + t] = ((float*)h2)[t];
}

// ---------------- launch ----------------
extern "C" void kernel_launch(void* const* d_in, const int* in_sizes, int n_in,
                              void* d_out, int out_size) {
    const float* xs     = (const float*)d_in[0];
    const int*   ei     = (const int*)  d_in[1];
    const float* W1     = (const float*)d_in[2];
    const float* a_src1 = (const float*)d_in[3];
    const float* a_dst1 = (const float*)d_in[4];
    const float* b1     = (const float*)d_in[5];
    const float* W2     = (const float*)d_in[6];
    const float* a_src2 = (const float*)d_in[7];
    const float* a_dst2 = (const float*)d_in[8];
    const float* b2     = (const float*)d_in[9];
    const float* Wih_f  = (const float*)d_in[10];
    const float* Whh_f  = (const float*)d_in[11];
    const float* bih_f  = (const float*)d_in[12];
    const float* bhh_f  = (const float*)d_in[13];
    const float* Wih_b  = (const float*)d_in[14];
    const float* Whh_b  = (const float*)d_in[15];
    const float* bih_b  = (const float*)d_in[16];
    const float* bhh_b  = (const float*)d_in[17];
    float* out = (float*)d_out;

    k_zero<<<(KSNAP * NNODE + 255) / 256, 256>>>();
    k_count<<<(KSNAP * EPTOT + 255) / 256, 256>>>(ei);
    k_scan<<<KSNAP, 1024>>>();
    k_scatter<<<(KSNAP * EPTOT + 255) / 256, 256>>>(ei);

    k_prep<<<1, 256>>>(W1, a_src1, a_dst1);

    dim3 gagg(NNODE / 8, KSNAP);
    k_agg1<<<gagg, 256>>>(xs);

    k_gemm<<<dim3(NTOT / 128, 2), 256>>>(W2, W1, b1, a_src2, a_dst2);
    k_agg2<<<gagg, 256>>>(b2);

    k_whhT<<<(2 * 128 * 1024 + 255) / 256, 256>>>(Whh_f, Whh_b);
    k_xw<<<2048, 256>>>(Wih_f, Wih_b);
    k_lstm<<<2, 1024>>>(bih_f, bhh_f, bih_b, bhh_b, out);
}

// round 6
// speedup vs baseline: 10.2695x; 10.2695x over previous
#include <cuda_runtime.h>
#include <cuda_bf16.h>
#include <cstdint>

// ---------------- problem constants ----------------
#define KSNAP 8
#define NNODE 10000
#define NEDGE 160000
#define EPTOT (NEDGE + NNODE)   // edges + self loops = 170000
#define HEADS 8
#define D2 256
#define LH 256
#define NEG 0.2f
#define NTOT (KSNAP * NNODE)    // 80000

// ---------------- static scratch ----------------
static __device__ unsigned int g_featb[NTOT * 128];    // h_lin bf16x2 packed
static __device__ float g_t   [NTOT * HEADS];          // layer-1 aggregated scalars per head
static __device__ float g_ssrc[NTOT * HEADS];
static __device__ float g_sdst[NTOT * HEADS];
static __device__ float g_q   [2 * HEADS];
static __device__ int   g_deg [KSNAP * NNODE];
static __device__ int   g_off [KSNAP * (NNODE + 1)];
static __device__ int   g_pos [KSNAP * NNODE];
static __device__ int   g_adj [KSNAP * EPTOT];
static __device__ float g_emb [KSNAP * D2];
static __device__ float g_xw  [2 * KSNAP * 4 * LH];
static __device__ float2 g_whhT2[2 * 128 * 1024];

// ---------------- helpers ----------------
__device__ __forceinline__ float warp_sum(float v) {
#pragma unroll
    for (int o = 16; o; o >>= 1) v += __shfl_xor_sync(0xffffffffu, v, o);
    return v;
}
__device__ __forceinline__ float warp_max(float v) {
#pragma unroll
    for (int o = 16; o; o >>= 1) v = fmaxf(v, __shfl_xor_sync(0xffffffffu, v, o));
    return v;
}
__device__ __forceinline__ float warp_min(float v) {
#pragma unroll
    for (int o = 16; o; o >>= 1) v = fminf(v, __shfl_xor_sync(0xffffffffu, v, o));
    return v;
}
#define FMA2(d, a, b) asm("fma.rn.f32x2 %0, %1, %2, %0;" : "+l"(d) : "l"(a), "l"(b))
__device__ __forceinline__ unsigned long long dup2(float a) {
    unsigned long long r;
    asm("mov.b64 %0, {%1, %1};" : "=l"(r) : "r"(__float_as_uint(a)));
    return r;
}
__device__ __forceinline__ void unpack2(unsigned long long v, float& lo, float& hi) {
    lo = __uint_as_float((unsigned int)(v & 0xffffffffull));
    hi = __uint_as_float((unsigned int)(v >> 32));
}
__device__ __forceinline__ float lky(float e) { return (e >= 0.f) ? e : NEG * e; }
__device__ __forceinline__ uint32_t pack_bf16x2(float a, float b) {
    __nv_bfloat162 p = __float22bfloat162_rn(make_float2(a, b));
    return *(uint32_t*)&p;
}

// ---------------- CSR build ----------------
__global__ void k_zero() {
    int i = blockIdx.x * blockDim.x + threadIdx.x;
    if (i < KSNAP * NNODE) g_deg[i] = 0;
    if (i < KSNAP * D2)    g_emb[i] = 0.f;
}

__global__ void k_count(const int* __restrict__ ei) {
    int idx = blockIdx.x * blockDim.x + threadIdx.x;
    if (idx >= KSNAP * EPTOT) return;
    int k = idx / EPTOT, e = idx % EPTOT;
    int dst = (e < NEDGE) ? ei[(k * 2 + 1) * NEDGE + e] : (e - NEDGE);
    atomicAdd(&g_deg[k * NNODE + dst], 1);
}

__global__ void k_scan() {
    __shared__ int part[1024];
    int k = blockIdx.x, t = threadIdx.x;
    int base = t * 10;
    int loc[10];
    int s = 0;
#pragma unroll
    for (int i = 0; i < 10; i++) {
        int n = base + i;
        int v = (n < NNODE) ? g_deg[k * NNODE + n] : 0;
        loc[i] = s; s += v;
    }
    part[t] = s;
    __syncthreads();
    for (int ofs = 1; ofs < 1024; ofs <<= 1) {
        int v = (t >= ofs) ? part[t - ofs] : 0;
        __syncthreads();
        part[t] += v;
        __syncthreads();
    }
    int pre = (t == 0) ? 0 : part[t - 1];
#pragma unroll
    for (int i = 0; i < 10; i++) {
        int n = base + i;
        if (n < NNODE) {
            int o = pre + loc[i];
            g_off[k * (NNODE + 1) + n] = o;
            g_pos[k * NNODE + n]       = o;
        }
    }
    if (t == 1023) g_off[k * (NNODE + 1) + NNODE] = part[1023];
}

__global__ void k_scatter(const int* __restrict__ ei) {
    int idx = blockIdx.x * blockDim.x + threadIdx.x;
    if (idx >= KSNAP * EPTOT) return;
    int k = idx / EPTOT, e = idx % EPTOT;
    int src, dst;
    if (e < NEDGE) {
        src = ei[(k * 2 + 0) * NEDGE + e];
        dst = ei[(k * 2 + 1) * NEDGE + e];
    } else {
        src = e - NEDGE;
        dst = e - NEDGE;
    }
    int slot = atomicAdd(&g_pos[k * NNODE + dst], 1);
    g_adj[k * EPTOT + slot] = src;
}

// ---------------- prep: q vectors ----------------
__global__ void k_prep(const float* __restrict__ W1, const float* __restrict__ as1,
                       const float* __restrict__ ad1) {
    int c = threadIdx.x;
    float w = W1[c];
    float vs = warp_sum(w * as1[c]);
    float vd = warp_sum(w * ad1[c]);
    if ((c & 31) == 0) {
        g_q[c >> 5] = vs;
        g_q[8 + (c >> 5)] = vd;
    }
}

// ---------------- layer-1 GAT, scalar, exact-max ----------------
__global__ __launch_bounds__(256) void k_agg1(const float* __restrict__ xs) {
    int k = blockIdx.y;
    int n = blockIdx.x * 8 + (threadIdx.x >> 5);
    int lane = threadIdx.x & 31;
    long base = (long)k * NNODE;
    int o0 = g_off[k * (NNODE + 1) + n];
    int o1 = g_off[k * (NNODE + 1) + n + 1];
    const int* adj = g_adj + (long)k * EPTOT;

    float qs[HEADS], dterm[HEADS];
    float xd = xs[base + n];
#pragma unroll
    for (int i = 0; i < HEADS; i++) { qs[i] = g_q[i]; dterm[i] = xd * g_q[8 + i]; }

    // pass 1: min/max of x over sources (exact max via monotonicity of leaky_relu)
    float xmx = -1e30f, xmn = 1e30f;
    for (int j = o0 + lane; j < o1; j += 32) {
        float xv = xs[base + adj[j]];
        xmx = fmaxf(xmx, xv); xmn = fminf(xmn, xv);
    }
    xmx = warp_max(xmx); xmn = warp_min(xmn);
    float m[HEADS];
#pragma unroll
    for (int i = 0; i < HEADS; i++)
        m[i] = lky(fmaf(qs[i], (qs[i] >= 0.f) ? xmx : xmn, dterm[i]));

    // pass 2: fused denominator + weighted sum
    float dsum[HEADS], tt[HEADS];
#pragma unroll
    for (int i = 0; i < HEADS; i++) { dsum[i] = 0.f; tt[i] = 0.f; }
    for (int j = o0 + lane; j < o1; j += 32) {
        float xv = xs[base + adj[j]];
#pragma unroll
        for (int i = 0; i < HEADS; i++) {
            float e = lky(fmaf(xv, qs[i], dterm[i]));
            float ex = __expf(e - m[i]);
            dsum[i] += ex;
            tt[i] = fmaf(ex, xv, tt[i]);
        }
    }
#pragma unroll
    for (int i = 0; i < HEADS; i++) {
        float ds = warp_sum(dsum[i]);
        float ts = warp_sum(tt[i]);
        if (lane == 0) g_t[(base + n) * HEADS + i] = ts / (ds + 1e-16f);
    }
}

// ---------------- FFMA2 GEMM: h_lin = relu(outer(t,W1)+b1) @ W2 ----------------
// A generated in registers (no A smem traffic); B f32 in smem; fp32 exact.
// launch_bounds(256, 1): full register budget -> NO spills (the (256,2) cap
// spilled the 64-reg accumulator set and cost ~4.5ms in R4/R5).
__global__ __launch_bounds__(256, 1) void k_gemm(const float* __restrict__ W2,
                                                 const float* __restrict__ W1,
                                                 const float* __restrict__ b1,
                                                 const float* __restrict__ as2,
                                                 const float* __restrict__ ad2) {
    __shared__ float t_sh[128][8];      // 4KB
    __shared__ float W1s[256], b1s[256];
    __shared__ float sAs[128], sAd[128];
    __shared__ float Bs[32][128];       // 16KB, one 32-k chunk (= one head)
    int tid = threadIdx.x;
    int tx = tid & 15, ty = tid >> 4;
    long m0 = (long)blockIdx.x * 128;
    int n0 = blockIdx.y * 128;

    W1s[tid] = W1[tid];
    b1s[tid] = b1[tid];
    if (tid < 128) { sAs[tid] = as2[n0 + tid]; sAd[tid] = ad2[n0 + tid]; }
    {
        int row = tid >> 1, part = tid & 1;
        *(float4*)&t_sh[row][part * 4] = *(const float4*)&g_t[(m0 + row) * 8 + part * 4];
    }
    __syncthreads();

    unsigned long long acc2[8][4];
#pragma unroll
    for (int r = 0; r < 8; r++)
#pragma unroll
        for (int p = 0; p < 4; p++) acc2[r][p] = 0ull;

    for (int ch = 0; ch < 8; ch++) {    // 8 chunks of 32 k (chunk == head)
        int k0 = ch * 32;
        // fill Bs: 32 rows x 128 cols
#pragma unroll
        for (int q = 0; q < 4; q++) {
            int id = tid + q * 256;
            int row = id >> 5, cq = id & 31;
            *(float4*)&Bs[row][cq * 4] = *(const float4*)&W2[(long)(k0 + row) * D2 + n0 + cq * 4];
        }
        __syncthreads();

        float tr[8];
#pragma unroll
        for (int r = 0; r < 8; r++) tr[r] = t_sh[ty * 8 + r][ch];

#pragma unroll 4
        for (int kk = 0; kk < 32; kk++) {
            float w = W1s[k0 + kk];
            float bb = b1s[k0 + kk];
            unsigned long long av[8];
#pragma unroll
            for (int r = 0; r < 8; r++)
                av[r] = dup2(fmaxf(fmaf(w, tr[r], bb), 0.f));
            ulonglong2 b01 = *(const ulonglong2*)&Bs[kk][tx * 8];
            ulonglong2 b23 = *(const ulonglong2*)&Bs[kk][tx * 8 + 4];
            unsigned long long bv[4] = {b01.x, b01.y, b23.x, b23.y};
#pragma unroll
            for (int r = 0; r < 8; r++)
#pragma unroll
                for (int p = 0; p < 4; p++) FMA2(acc2[r][p], av[r], bv[p]);
        }
        __syncthreads();
    }

    float accf[8][8];
#pragma unroll
    for (int r = 0; r < 8; r++)
#pragma unroll
        for (int p = 0; p < 4; p++) unpack2(acc2[r][p], accf[r][2 * p], accf[r][2 * p + 1]);

    // store features as bf16x2
#pragma unroll
    for (int r = 0; r < 8; r++) {
        long row = m0 + ty * 8 + r;
        uint4 pkd = make_uint4(pack_bf16x2(accf[r][0], accf[r][1]),
                               pack_bf16x2(accf[r][2], accf[r][3]),
                               pack_bf16x2(accf[r][4], accf[r][5]),
                               pack_bf16x2(accf[r][6], accf[r][7]));
        *(uint4*)&g_featb[row * 128 + n0 / 2 + tx * 4] = pkd;
    }

    // s-vectors: 4-lane groups own one head (32 cols)
    float avs[8], avd[8];
#pragma unroll
    for (int q = 0; q < 8; q++) {
        avs[q] = sAs[tx * 8 + q];
        avd[q] = sAd[tx * 8 + q];
    }
    int head = (n0 >> 5) + (tx >> 2);
#pragma unroll
    for (int r = 0; r < 8; r++) {
        float ss = 0.f, sd = 0.f;
#pragma unroll
        for (int q = 0; q < 8; q++) {
            ss = fmaf(accf[r][q], avs[q], ss);
            sd = fmaf(accf[r][q], avd[q], sd);
        }
        ss += __shfl_xor_sync(0xffffffffu, ss, 1);
        ss += __shfl_xor_sync(0xffffffffu, ss, 2);
        sd += __shfl_xor_sync(0xffffffffu, sd, 1);
        sd += __shfl_xor_sync(0xffffffffu, sd, 2);
        if ((tx & 3) == 0) {
            long row = m0 + ty * 8 + r;
            g_ssrc[row * HEADS + head] = ss;
            g_sdst[row * HEADS + head] = sd;
        }
    }
}

// ---------------- layer-2 GAT aggregation + CTA-pooled mean ----------------
__global__ __launch_bounds__(256) void k_agg2(const float* __restrict__ bias) {
    __shared__ float s_m[8][8];
    __shared__ float pool[8][256];   // per-warp output rows, reduced at the end
    int k = blockIdx.y;
    int w = threadIdx.x >> 5;
    int n = blockIdx.x * 8 + w;
    int lane = threadIdx.x & 31;
    long base = (long)k * NNODE;
    int o0 = g_off[k * (NNODE + 1) + n];
    int o1 = g_off[k * (NNODE + 1) + n + 1];
    const int* adj = g_adj + (long)k * EPTOT;

    float sd[HEADS];
    {
        float4 d0 = *(const float4*)&g_sdst[(base + n) * HEADS];
        float4 d1 = *(const float4*)&g_sdst[(base + n) * HEADS + 4];
        sd[0] = d0.x; sd[1] = d0.y; sd[2] = d0.z; sd[3] = d0.w;
        sd[4] = d1.x; sd[5] = d1.y; sd[6] = d1.z; sd[7] = d1.w;
    }

    // pass 1: per-head max of ssrc over sources (exact; leaky is monotone)
    float mx[HEADS];
#pragma unroll
    for (int i = 0; i < HEADS; i++) mx[i] = -1e30f;
    for (int j = o0 + lane; j < o1; j += 32) {
        const float4* sp = (const float4*)&g_ssrc[((long)base + adj[j]) * HEADS];
        float4 s0 = sp[0], s1 = sp[1];
        mx[0] = fmaxf(mx[0], s0.x); mx[1] = fmaxf(mx[1], s0.y);
        mx[2] = fmaxf(mx[2], s0.z); mx[3] = fmaxf(mx[3], s0.w);
        mx[4] = fmaxf(mx[4], s1.x); mx[5] = fmaxf(mx[5], s1.y);
        mx[6] = fmaxf(mx[6], s1.z); mx[7] = fmaxf(mx[7], s1.w);
    }
#pragma unroll
    for (int i = 0; i < HEADS; i++) mx[i] = warp_max(mx[i]);
    if (lane == 0) {
#pragma unroll
        for (int i = 0; i < HEADS; i++) s_m[w][i] = lky(mx[i] + sd[i]);
    }
    __syncwarp();

    int hl = lane >> 2;
    float m_l = s_m[w][hl];
    float sd_l = sd[hl];

    // pass 2 (serial per warp): fused denominator + weighted bf16 gather
    float dsum = 0.f;
    float a0 = 0.f, a1 = 0.f, a2 = 0.f, a3 = 0.f, a4 = 0.f, a5 = 0.f, a6 = 0.f, a7 = 0.f;
    for (int j = o0; j < o1; j++) {
        long s = adj[j];
        float e = lky(g_ssrc[(base + s) * HEADS + hl] + sd_l);
        float al = __expf(e - m_l);
        dsum += al;
        uint4 fv = *(const uint4*)&g_featb[(base + s) * 128 + lane * 4];
        float2 f0 = __bfloat1622float2(*(__nv_bfloat162*)&fv.x);
        float2 f1 = __bfloat1622float2(*(__nv_bfloat162*)&fv.y);
        float2 f2 = __bfloat1622float2(*(__nv_bfloat162*)&fv.z);
        float2 f3 = __bfloat1622float2(*(__nv_bfloat162*)&fv.w);
        a0 = fmaf(f0.x, al, a0); a1 = fmaf(f0.y, al, a1);
        a2 = fmaf(f1.x, al, a2); a3 = fmaf(f1.y, al, a3);
        a4 = fmaf(f2.x, al, a4); a5 = fmaf(f2.y, al, a5);
        a6 = fmaf(f3.x, al, a6); a7 = fmaf(f3.y, al, a7);
    }
    float inv = 1.f / (dsum + 1e-16f);
    float4 b0 = *(const float4*)&bias[lane * 8];
    float4 b1v = *(const float4*)&bias[lane * 8 + 4];
    float* pw = &pool[w][lane * 8];
    pw[0] = fmaxf(fmaf(a0, inv, b0.x), 0.f);
    pw[1] = fmaxf(fmaf(a1, inv, b0.y), 0.f);
    pw[2] = fmaxf(fmaf(a2, inv, b0.z), 0.f);
    pw[3] = fmaxf(fmaf(a3, inv, b0.w), 0.f);
    pw[4] = fmaxf(fmaf(a4, inv, b1v.x), 0.f);
    pw[5] = fmaxf(fmaf(a5, inv, b1v.y), 0.f);
    pw[6] = fmaxf(fmaf(a6, inv, b1v.z), 0.f);
    pw[7] = fmaxf(fmaf(a7, inv, b1v.w), 0.f);
    __syncthreads();

    // CTA reduction over the 8 node rows, one global atomic per channel
    int c = threadIdx.x;   // 256 channels
    float s8 = pool[0][c] + pool[1][c] + pool[2][c] + pool[3][c]
             + pool[4][c] + pool[5][c] + pool[6][c] + pool[7][c];
    atomicAdd(&g_emb[k * D2 + c], s8 * (1.0f / NNODE));
}

// ---------------- LSTM input projections ----------------
__global__ void k_xw(const float* __restrict__ Wih_f, const float* __restrict__ Wih_b) {
    int gid = blockIdx.x * 8 + (threadIdx.x >> 5);
    int lane = threadIdx.x & 31;
    int d = gid >> 13;
    int rem = gid & 8191;
    int k = rem >> 10;
    int g = rem & 1023;
    const float* Wih = d ? Wih_b : Wih_f;
    float s = 0.f;
    for (int j = lane; j < D2; j += 32)
        s += Wih[g * D2 + j] * g_emb[k * D2 + j];
    s = warp_sum(s);
    if (lane == 0) g_xw[gid] = s;
}

__global__ void k_whhT(const float* __restrict__ Whh_f, const float* __restrict__ Whh_b) {
    int idx = blockIdx.x * blockDim.x + threadIdx.x;
    if (idx >= 2 * 128 * 1024) return;
    int d = idx >> 17;
    int r = idx & ((1 << 17) - 1);
    int j2 = r >> 10;
    int t = r & 1023;
    const float* W = d ? Whh_b : Whh_f;
    g_whhT2[(((long)d * 128 + j2) << 10) + t] = make_float2(W[t * 256 + 2 * j2], W[t * 256 + 2 * j2 + 1]);
}

// ---------------- bidirectional LSTM ----------------
__global__ __launch_bounds__(1024) void k_lstm(const float* __restrict__ bih_f, const float* __restrict__ bhh_f,
                                               const float* __restrict__ bih_b, const float* __restrict__ bhh_b,
                                               float* __restrict__ out) {
    int d = blockIdx.x;
    int t = threadIdx.x;
    __shared__ float2 h2[LH / 2];
    __shared__ float cc[LH], gbuf[4 * LH];
    if (t < LH / 2) h2[t] = make_float2(0.f, 0.f);
    if (t < LH) cc[t] = 0.f;
    const float* bih = d ? bih_b : bih_f;
    const float* bhh = d ? bhh_b : bhh_f;
    const unsigned long long* WT = (const unsigned long long*)(g_whhT2 + (long)d * 128 * 1024);
    const unsigned long long* hp = (const unsigned long long*)h2;
    float bsum = bih[t] + bhh[t];
    __syncthreads();
    for (int step = 0; step < KSNAP; step++) {
        int kk = d ? (KSNAP - 1 - step) : step;
        unsigned long long acc2 = 0ull;
#pragma unroll 8
        for (int j2 = 0; j2 < LH / 2; j2++) {
            unsigned long long w = WT[(long)j2 * 1024 + t];
            unsigned long long hh = hp[j2];
            FMA2(acc2, w, hh);
        }
        float lo, hi;
        unpack2(acc2, lo, hi);
        gbuf[t] = lo + hi + g_xw[((long)d * KSNAP + kk) * 1024 + t] + bsum;
        __syncthreads();
        if (t < LH) {
            float ig = 1.f / (1.f + expf(-gbuf[t]));
            float fg = 1.f / (1.f + expf(-gbuf[LH + t]));
            float gg = tanhf(gbuf[2 * LH + t]);
            float og = 1.f / (1.f + expf(-gbuf[3 * LH + t]));
            float cn = fg * cc[t] + ig * gg;
            cc[t] = cn;
            ((float*)h2)[t] = og * tanhf(cn);
        }
        __syncthreads();
    }
    if (t < LH) out[d * LH + t] = ((float*)h2)[t];
}

// ---------------- launch ----------------
extern "C" void kernel_launch(void* const* d_in, const int* in_sizes, int n_in,
                              void* d_out, int out_size) {
    const float* xs     = (const float*)d_in[0];
    const int*   ei     = (const int*)  d_in[1];
    const float* W1     = (const float*)d_in[2];
    const float* a_src1 = (const float*)d_in[3];
    const float* a_dst1 = (const float*)d_in[4];
    const float* b1     = (const float*)d_in[5];
    const float* W2     = (const float*)d_in[6];
    const float* a_src2 = (const float*)d_in[7];
    const float* a_dst2 = (const float*)d_in[8];
    const float* b2     = (const float*)d_in[9];
    const float* Wih_f  = (const float*)d_in[10];
    const float* Whh_f  = (const float*)d_in[11];
    const float* bih_f  = (const float*)d_in[12];
    const float* bhh_f  = (const float*)d_in[13];
    const float* Wih_b  = (const float*)d_in[14];
    const float* Whh_b  = (const float*)d_in[15];
    const float* bih_b  = (const float*)d_in[16];
    const float* bhh_b  = (const float*)d_in[17];
    float* out = (float*)d_out;

    k_zero<<<(KSNAP * NNODE + 255) / 256, 256>>>();
    k_count<<<(KSNAP * EPTOT + 255) / 256, 256>>>(ei);
    k_scan<<<KSNAP, 1024>>>();
    k_scatter<<<(KSNAP * EPTOT + 255) / 256, 256>>>(ei);

    k_prep<<<1, 256>>>(W1, a_src1, a_dst1);

    dim3 gagg(NNODE / 8, KSNAP);
    k_agg1<<<gagg, 256>>>(xs);

    k_gemm<<<dim3(NTOT / 128, 2), 256>>>(W2, W1, b1, a_src2, a_dst2);
    k_agg2<<<gagg, 256>>>(b2);

    k_whhT<<<(2 * 128 * 1024 + 255) / 256, 256>>>(Whh_f, Whh_b);
    k_xw<<<2048, 256>>>(Wih_f, Wih_b);
    k_lstm<<<2, 1024>>>(bih_f, bhh_f, bih_b, bhh_b, out);
}

// round 7
// speedup vs baseline: 10.9234x; 1.0637x over previous
#include <cuda_runtime.h>
#include <cuda_bf16.h>
#include <cstdint>

// ---------------- problem constants ----------------
#define KSNAP 8
#define NNODE 10000
#define NEDGE 160000
#define EPTOT (NEDGE + NNODE)   // edges + self loops = 170000
#define HEADS 8
#define D2 256
#define LH 256
#define NEG 0.2f
#define NTOT (KSNAP * NNODE)    // 80000

// ---------------- static scratch ----------------
static __device__ unsigned int g_featb[NTOT * 128];    // h_lin bf16x2 packed
static __device__ float g_t   [NTOT * HEADS];          // layer-1 aggregated scalars per head
static __device__ float g_ssrc[NTOT * HEADS];
static __device__ float g_sdst[NTOT * HEADS];
static __device__ float g_q   [2 * HEADS];
static __device__ int   g_deg [KSNAP * NNODE];
static __device__ int   g_off [KSNAP * (NNODE + 1)];
static __device__ int   g_pos [KSNAP * NNODE];
static __device__ int   g_adj [KSNAP * EPTOT];
static __device__ float g_emb [KSNAP * D2];
static __device__ float g_xw  [2 * KSNAP * 4 * LH];
static __device__ float2 g_whhT2[2 * 128 * 1024];

// ---------------- helpers ----------------
__device__ __forceinline__ float warp_sum(float v) {
#pragma unroll
    for (int o = 16; o; o >>= 1) v += __shfl_xor_sync(0xffffffffu, v, o);
    return v;
}
__device__ __forceinline__ float warp_max(float v) {
#pragma unroll
    for (int o = 16; o; o >>= 1) v = fmaxf(v, __shfl_xor_sync(0xffffffffu, v, o));
    return v;
}
__device__ __forceinline__ float warp_min(float v) {
#pragma unroll
    for (int o = 16; o; o >>= 1) v = fminf(v, __shfl_xor_sync(0xffffffffu, v, o));
    return v;
}
#define FMA2(d, a, b) asm("fma.rn.f32x2 %0, %1, %2, %0;" : "+l"(d) : "l"(a), "l"(b))
__device__ __forceinline__ unsigned long long dup2(float a) {
    unsigned long long r;
    asm("mov.b64 %0, {%1, %1};" : "=l"(r) : "r"(__float_as_uint(a)));
    return r;
}
__device__ __forceinline__ void unpack2(unsigned long long v, float& lo, float& hi) {
    lo = __uint_as_float((unsigned int)(v & 0xffffffffull));
    hi = __uint_as_float((unsigned int)(v >> 32));
}
__device__ __forceinline__ float lky(float e) { return (e >= 0.f) ? e : NEG * e; }
__device__ __forceinline__ uint32_t pack_bf16x2(float a, float b) {
    __nv_bfloat162 p = __float22bfloat162_rn(make_float2(a, b));
    return *(uint32_t*)&p;
}
__device__ __forceinline__ uint32_t smem_u32(const void* p) {
    uint32_t a;
    asm("{ .reg .u64 t; cvta.to.shared.u64 t, %1; cvt.u32.u64 %0, t; }" : "=r"(a) : "l"(p));
    return a;
}
__device__ __forceinline__ uint32_t cluster_rank() {
    uint32_t r;
    asm("mov.u32 %0, %%cluster_ctarank;" : "=r"(r));
    return r;
}
__device__ __forceinline__ float dsmem_ld(uint32_t addr, uint32_t rank) {
    uint32_t ra; float v;
    asm("mapa.shared::cluster.u32 %0, %1, %2;" : "=r"(ra) : "r"(addr), "r"(rank));
    asm volatile("ld.shared::cluster.f32 %0, [%1];" : "=f"(v) : "r"(ra));
    return v;
}
#define CLUSTER_SYNC() do {                                            \
    asm volatile("barrier.cluster.arrive.aligned;" ::: "memory");      \
    asm volatile("barrier.cluster.wait.aligned;" ::: "memory");        \
} while (0)

// ---------------- CSR build ----------------
__global__ void k_zero() {
    int i = blockIdx.x * blockDim.x + threadIdx.x;
    if (i < KSNAP * NNODE) g_deg[i] = 0;
    if (i < KSNAP * D2)    g_emb[i] = 0.f;
}

__global__ void k_count(const int* __restrict__ ei) {
    int idx = blockIdx.x * blockDim.x + threadIdx.x;
    if (idx >= KSNAP * EPTOT) return;
    int k = idx / EPTOT, e = idx % EPTOT;
    int dst = (e < NEDGE) ? ei[(k * 2 + 1) * NEDGE + e] : (e - NEDGE);
    atomicAdd(&g_deg[k * NNODE + dst], 1);
}

__global__ void k_scan() {
    __shared__ int part[1024];
    int k = blockIdx.x, t = threadIdx.x;
    int base = t * 10;
    int loc[10];
    int s = 0;
#pragma unroll
    for (int i = 0; i < 10; i++) {
        int n = base + i;
        int v = (n < NNODE) ? g_deg[k * NNODE + n] : 0;
        loc[i] = s; s += v;
    }
    part[t] = s;
    __syncthreads();
    for (int ofs = 1; ofs < 1024; ofs <<= 1) {
        int v = (t >= ofs) ? part[t - ofs] : 0;
        __syncthreads();
        part[t] += v;
        __syncthreads();
    }
    int pre = (t == 0) ? 0 : part[t - 1];
#pragma unroll
    for (int i = 0; i < 10; i++) {
        int n = base + i;
        if (n < NNODE) {
            int o = pre + loc[i];
            g_off[k * (NNODE + 1) + n] = o;
            g_pos[k * NNODE + n]       = o;
        }
    }
    if (t == 1023) g_off[k * (NNODE + 1) + NNODE] = part[1023];
}

__global__ void k_scatter(const int* __restrict__ ei) {
    int idx = blockIdx.x * blockDim.x + threadIdx.x;
    if (idx >= KSNAP * EPTOT) return;
    int k = idx / EPTOT, e = idx % EPTOT;
    int src, dst;
    if (e < NEDGE) {
        src = ei[(k * 2 + 0) * NEDGE + e];
        dst = ei[(k * 2 + 1) * NEDGE + e];
    } else {
        src = e - NEDGE;
        dst = e - NEDGE;
    }
    int slot = atomicAdd(&g_pos[k * NNODE + dst], 1);
    g_adj[k * EPTOT + slot] = src;
}

// ---------------- prep: q vectors ----------------
__global__ void k_prep(const float* __restrict__ W1, const float* __restrict__ as1,
                       const float* __restrict__ ad1) {
    int c = threadIdx.x;
    float w = W1[c];
    float vs = warp_sum(w * as1[c]);
    float vd = warp_sum(w * ad1[c]);
    if ((c & 31) == 0) {
        g_q[c >> 5] = vs;
        g_q[8 + (c >> 5)] = vd;
    }
}

// ---------------- layer-1 GAT, scalar, exact-max ----------------
__global__ __launch_bounds__(256) void k_agg1(const float* __restrict__ xs) {
    int k = blockIdx.y;
    int n = blockIdx.x * 8 + (threadIdx.x >> 5);
    int lane = threadIdx.x & 31;
    long base = (long)k * NNODE;
    int o0 = g_off[k * (NNODE + 1) + n];
    int o1 = g_off[k * (NNODE + 1) + n + 1];
    const int* adj = g_adj + (long)k * EPTOT;

    float qs[HEADS], dterm[HEADS];
    float xd = xs[base + n];
#pragma unroll
    for (int i = 0; i < HEADS; i++) { qs[i] = g_q[i]; dterm[i] = xd * g_q[8 + i]; }

    float xmx = -1e30f, xmn = 1e30f;
    for (int j = o0 + lane; j < o1; j += 32) {
        float xv = xs[base + adj[j]];
        xmx = fmaxf(xmx, xv); xmn = fminf(xmn, xv);
    }
    xmx = warp_max(xmx); xmn = warp_min(xmn);
    float m[HEADS];
#pragma unroll
    for (int i = 0; i < HEADS; i++)
        m[i] = lky(fmaf(qs[i], (qs[i] >= 0.f) ? xmx : xmn, dterm[i]));

    float dsum[HEADS], tt[HEADS];
#pragma unroll
    for (int i = 0; i < HEADS; i++) { dsum[i] = 0.f; tt[i] = 0.f; }
    for (int j = o0 + lane; j < o1; j += 32) {
        float xv = xs[base + adj[j]];
#pragma unroll
        for (int i = 0; i < HEADS; i++) {
            float e = lky(fmaf(xv, qs[i], dterm[i]));
            float ex = __expf(e - m[i]);
            dsum[i] += ex;
            tt[i] = fmaf(ex, xv, tt[i]);
        }
    }
#pragma unroll
    for (int i = 0; i < HEADS; i++) {
        float ds = warp_sum(dsum[i]);
        float ts = warp_sum(tt[i]);
        if (lane == 0) g_t[(base + n) * HEADS + i] = ts / (ds + 1e-16f);
    }
}

// ---------------- FFMA2 GEMM: h_lin = relu(outer(t,W1)+b1) @ W2 ----------------
__global__ __launch_bounds__(256, 1) void k_gemm(const float* __restrict__ W2,
                                                 const float* __restrict__ W1,
                                                 const float* __restrict__ b1,
                                                 const float* __restrict__ as2,
                                                 const float* __restrict__ ad2) {
    __shared__ float t_sh[128][8];
    __shared__ float W1s[256], b1s[256];
    __shared__ float sAs[128], sAd[128];
    __shared__ float Bs[32][128];
    int tid = threadIdx.x;
    int tx = tid & 15, ty = tid >> 4;
    long m0 = (long)blockIdx.x * 128;
    int n0 = blockIdx.y * 128;

    W1s[tid] = W1[tid];
    b1s[tid] = b1[tid];
    if (tid < 128) { sAs[tid] = as2[n0 + tid]; sAd[tid] = ad2[n0 + tid]; }
    {
        int row = tid >> 1, part = tid & 1;
        *(float4*)&t_sh[row][part * 4] = *(const float4*)&g_t[(m0 + row) * 8 + part * 4];
    }
    __syncthreads();

    unsigned long long acc2[8][4];
#pragma unroll
    for (int r = 0; r < 8; r++)
#pragma unroll
        for (int p = 0; p < 4; p++) acc2[r][p] = 0ull;

    for (int ch = 0; ch < 8; ch++) {
        int k0 = ch * 32;
#pragma unroll
        for (int q = 0; q < 4; q++) {
            int id = tid + q * 256;
            int row = id >> 5, cq = id & 31;
            *(float4*)&Bs[row][cq * 4] = *(const float4*)&W2[(long)(k0 + row) * D2 + n0 + cq * 4];
        }
        __syncthreads();

        float tr[8];
#pragma unroll
        for (int r = 0; r < 8; r++) tr[r] = t_sh[ty * 8 + r][ch];

#pragma unroll 4
        for (int kk = 0; kk < 32; kk++) {
            float w = W1s[k0 + kk];
            float bb = b1s[k0 + kk];
            unsigned long long av[8];
#pragma unroll
            for (int r = 0; r < 8; r++)
                av[r] = dup2(fmaxf(fmaf(w, tr[r], bb), 0.f));
            ulonglong2 b01 = *(const ulonglong2*)&Bs[kk][tx * 8];
            ulonglong2 b23 = *(const ulonglong2*)&Bs[kk][tx * 8 + 4];
            unsigned long long bv[4] = {b01.x, b01.y, b23.x, b23.y};
#pragma unroll
            for (int r = 0; r < 8; r++)
#pragma unroll
                for (int p = 0; p < 4; p++) FMA2(acc2[r][p], av[r], bv[p]);
        }
        __syncthreads();
    }

    float accf[8][8];
#pragma unroll
    for (int r = 0; r < 8; r++)
#pragma unroll
        for (int p = 0; p < 4; p++) unpack2(acc2[r][p], accf[r][2 * p], accf[r][2 * p + 1]);

#pragma unroll
    for (int r = 0; r < 8; r++) {
        long row = m0 + ty * 8 + r;
        uint4 pkd = make_uint4(pack_bf16x2(accf[r][0], accf[r][1]),
                               pack_bf16x2(accf[r][2], accf[r][3]),
                               pack_bf16x2(accf[r][4], accf[r][5]),
                               pack_bf16x2(accf[r][6], accf[r][7]));
        *(uint4*)&g_featb[row * 128 + n0 / 2 + tx * 4] = pkd;
    }

    float avs[8], avd[8];
#pragma unroll
    for (int q = 0; q < 8; q++) {
        avs[q] = sAs[tx * 8 + q];
        avd[q] = sAd[tx * 8 + q];
    }
    int head = (n0 >> 5) + (tx >> 2);
#pragma unroll
    for (int r = 0; r < 8; r++) {
        float ss = 0.f, sd = 0.f;
#pragma unroll
        for (int q = 0; q < 8; q++) {
            ss = fmaf(accf[r][q], avs[q], ss);
            sd = fmaf(accf[r][q], avd[q], sd);
        }
        ss += __shfl_xor_sync(0xffffffffu, ss, 1);
        ss += __shfl_xor_sync(0xffffffffu, ss, 2);
        sd += __shfl_xor_sync(0xffffffffu, sd, 1);
        sd += __shfl_xor_sync(0xffffffffu, sd, 2);
        if ((tx & 3) == 0) {
            long row = m0 + ty * 8 + r;
            g_ssrc[row * HEADS + head] = ss;
            g_sdst[row * HEADS + head] = sd;
        }
    }
}

// ---------------- layer-2 GAT aggregation + CTA-pooled mean ----------------
__global__ __launch_bounds__(256) void k_agg2(const float* __restrict__ bias) {
    __shared__ float s_m[8][8];
    __shared__ float pool[8][256];
    int k = blockIdx.y;
    int w = threadIdx.x >> 5;
    int n = blockIdx.x * 8 + w;
    int lane = threadIdx.x & 31;
    long base = (long)k * NNODE;
    int o0 = g_off[k * (NNODE + 1) + n];
    int o1 = g_off[k * (NNODE + 1) + n + 1];
    const int* adj = g_adj + (long)k * EPTOT;

    float sd[HEADS];
    {
        float4 d0 = *(const float4*)&g_sdst[(base + n) * HEADS];
        float4 d1 = *(const float4*)&g_sdst[(base + n) * HEADS + 4];
        sd[0] = d0.x; sd[1] = d0.y; sd[2] = d0.z; sd[3] = d0.w;
        sd[4] = d1.x; sd[5] = d1.y; sd[6] = d1.z; sd[7] = d1.w;
    }

    float mx[HEADS];
#pragma unroll
    for (int i = 0; i < HEADS; i++) mx[i] = -1e30f;
    for (int j = o0 + lane; j < o1; j += 32) {
        const float4* sp = (const float4*)&g_ssrc[((long)base + adj[j]) * HEADS];
        float4 s0 = sp[0], s1 = sp[1];
        mx[0] = fmaxf(mx[0], s0.x); mx[1] = fmaxf(mx[1], s0.y);
        mx[2] = fmaxf(mx[2], s0.z); mx[3] = fmaxf(mx[3], s0.w);
        mx[4] = fmaxf(mx[4], s1.x); mx[5] = fmaxf(mx[5], s1.y);
        mx[6] = fmaxf(mx[6], s1.z); mx[7] = fmaxf(mx[7], s1.w);
    }
#pragma unroll
    for (int i = 0; i < HEADS; i++) mx[i] = warp_max(mx[i]);
    if (lane == 0) {
#pragma unroll
        for (int i = 0; i < HEADS; i++) s_m[w][i] = lky(mx[i] + sd[i]);
    }
    __syncwarp();

    int hl = lane >> 2;
    float m_l = s_m[w][hl];
    float sd_l = sd[hl];

    float dsum = 0.f;
    float a0 = 0.f, a1 = 0.f, a2 = 0.f, a3 = 0.f, a4 = 0.f, a5 = 0.f, a6 = 0.f, a7 = 0.f;
    for (int j = o0; j < o1; j++) {
        long s = adj[j];
        float e = lky(g_ssrc[(base + s) * HEADS + hl] + sd_l);
        float al = __expf(e - m_l);
        dsum += al;
        uint4 fv = *(const uint4*)&g_featb[(base + s) * 128 + lane * 4];
        float2 f0 = __bfloat1622float2(*(__nv_bfloat162*)&fv.x);
        float2 f1 = __bfloat1622float2(*(__nv_bfloat162*)&fv.y);
        float2 f2 = __bfloat1622float2(*(__nv_bfloat162*)&fv.z);
        float2 f3 = __bfloat1622float2(*(__nv_bfloat162*)&fv.w);
        a0 = fmaf(f0.x, al, a0); a1 = fmaf(f0.y, al, a1);
        a2 = fmaf(f1.x, al, a2); a3 = fmaf(f1.y, al, a3);
        a4 = fmaf(f2.x, al, a4); a5 = fmaf(f2.y, al, a5);
        a6 = fmaf(f3.x, al, a6); a7 = fmaf(f3.y, al, a7);
    }
    float inv = 1.f / (dsum + 1e-16f);
    float4 b0 = *(const float4*)&bias[lane * 8];
    float4 b1v = *(const float4*)&bias[lane * 8 + 4];
    float* pw = &pool[w][lane * 8];
    pw[0] = fmaxf(fmaf(a0, inv, b0.x), 0.f);
    pw[1] = fmaxf(fmaf(a1, inv, b0.y), 0.f);
    pw[2] = fmaxf(fmaf(a2, inv, b0.z), 0.f);
    pw[3] = fmaxf(fmaf(a3, inv, b0.w), 0.f);
    pw[4] = fmaxf(fmaf(a4, inv, b1v.x), 0.f);
    pw[5] = fmaxf(fmaf(a5, inv, b1v.y), 0.f);
    pw[6] = fmaxf(fmaf(a6, inv, b1v.z), 0.f);
    pw[7] = fmaxf(fmaf(a7, inv, b1v.w), 0.f);
    __syncthreads();

    int c = threadIdx.x;
    float s8 = pool[0][c] + pool[1][c] + pool[2][c] + pool[3][c]
             + pool[4][c] + pool[5][c] + pool[6][c] + pool[7][c];
    atomicAdd(&g_emb[k * D2 + c], s8 * (1.0f / NNODE));
}

// ---------------- LSTM input projections ----------------
__global__ void k_xw(const float* __restrict__ Wih_f, const float* __restrict__ Wih_b) {
    int gid = blockIdx.x * 8 + (threadIdx.x >> 5);
    int lane = threadIdx.x & 31;
    int d = gid >> 13;
    int rem = gid & 8191;
    int k = rem >> 10;
    int g = rem & 1023;
    const float* Wih = d ? Wih_b : Wih_f;
    float s = 0.f;
    for (int j = lane; j < D2; j += 32)
        s += Wih[g * D2 + j] * g_emb[k * D2 + j];
    s = warp_sum(s);
    if (lane == 0) g_xw[gid] = s;
}

__global__ void k_whhT(const float* __restrict__ Whh_f, const float* __restrict__ Whh_b) {
    int idx = blockIdx.x * blockDim.x + threadIdx.x;
    if (idx >= 2 * 128 * 1024) return;
    int d = idx >> 17;
    int r = idx & ((1 << 17) - 1);
    int j2 = r >> 10;
    int t = r & 1023;
    const float* W = d ? Whh_b : Whh_f;
    g_whhT2[(((long)d * 128 + j2) << 10) + t] = make_float2(W[t * 256 + 2 * j2], W[t * 256 + 2 * j2 + 1]);
}

// ---------------- bidirectional LSTM: 4-CTA cluster per direction, split-j + DSMEM ----------------
__global__ __launch_bounds__(1024) __cluster_dims__(4, 1, 1)
void k_lstm(const float* __restrict__ bih_f, const float* __restrict__ bhh_f,
            const float* __restrict__ bih_b, const float* __restrict__ bhh_b,
            float* __restrict__ out) {
    int d = blockIdx.x >> 2;                 // direction
    uint32_t rank = cluster_rank();          // 0..3: owns h channels [rank*64, rank*64+64)
    int t = threadIdx.x;

    __shared__ __align__(16) float ps[2][1024];   // partial gate sums (double-buffered)
    __shared__ __align__(16) float hloc[64];      // my 64 h channels
    __shared__ float g4[256];                     // full gate values for my 64 channels
    __shared__ float xw_s[KSNAP][256];            // staged x-projections (+biases) for my gates

    const float* bih = d ? bih_b : bih_f;
    const float* bhh = d ? bhh_b : bhh_f;

    // my gate index for threads t<256: gate (t>>6) of channel rank*64 + (t&63)
    int gidx = (t >> 6) * 256 + rank * 64 + (t & 63);
    if (t < 256) {
        float bsum = bih[gidx] + bhh[gidx];
#pragma unroll
        for (int k = 0; k < KSNAP; k++) {
            int kk = d ? (KSNAP - 1 - k) : k;
            xw_s[k][t] = g_xw[((long)d * KSNAP + kk) * 1024 + gidx] + bsum;
        }
    }
    if (t < 64) hloc[t] = 0.f;
    float cstate = 0.f;

    const unsigned long long* WT =
        (const unsigned long long*)(g_whhT2 + (long)d * 128 * 1024) + (long)(rank * 32) * 1024 + t;
    const unsigned long long* hp = (const unsigned long long*)hloc;
    uint32_t ps_base = smem_u32(&ps[0][0]);

    __syncthreads();
    CLUSTER_SYNC();   // all CTAs initialized before first DSMEM access cycle

    int b = 0;
    for (int step = 0; step < KSNAP; step++) {
        // 1) partial gate sums over my 32 h-pairs, for ALL 1024 gates
        unsigned long long acc2 = 0ull;
#pragma unroll
        for (int jj = 0; jj < 32; jj++)
            FMA2(acc2, WT[(long)jj * 1024], hp[jj]);
        float lo, hi;
        unpack2(acc2, lo, hi);
        ps[b][t] = lo + hi;
        __syncthreads();
        CLUSTER_SYNC();   // ps[b] visible cluster-wide

        // 2) gather 4 partials for my 256 gate entries
        if (t < 256) {
            uint32_t pa = ps_base + (b * 1024 + gidx) * 4;
            float v = xw_s[step][t];
            v += dsmem_ld(pa, 0);
            v += dsmem_ld(pa, 1);
            v += dsmem_ld(pa, 2);
            v += dsmem_ld(pa, 3);
            g4[t] = v;
        }
        __syncthreads();

        // 3) h/c update for my 64 channels
        if (t < 64) {
            float ig = 1.f / (1.f + expf(-g4[t]));
            float fg = 1.f / (1.f + expf(-g4[64 + t]));
            float gg = tanhf(g4[128 + t]);
            float og = 1.f / (1.f + expf(-g4[192 + t]));
            cstate = fg * cstate + ig * gg;
            hloc[t] = og * tanhf(cstate);
        }
        __syncthreads();
        b ^= 1;
    }

    if (t < 64) out[d * LH + rank * 64 + t] = hloc[t];
    CLUSTER_SYNC();   // no CTA exits while peers may still read its ps
}

// ---------------- launch ----------------
extern "C" void kernel_launch(void* const* d_in, const int* in_sizes, int n_in,
                              void* d_out, int out_size) {
    const float* xs     = (const float*)d_in[0];
    const int*   ei     = (const int*)  d_in[1];
    const float* W1     = (const float*)d_in[2];
    const float* a_src1 = (const float*)d_in[3];
    const float* a_dst1 = (const float*)d_in[4];
    const float* b1     = (const float*)d_in[5];
    const float* W2     = (const float*)d_in[6];
    const float* a_src2 = (const float*)d_in[7];
    const float* a_dst2 = (const float*)d_in[8];
    const float* b2     = (const float*)d_in[9];
    const float* Wih_f  = (const float*)d_in[10];
    const float* Whh_f  = (const float*)d_in[11];
    const float* bih_f  = (const float*)d_in[12];
    const float* bhh_f  = (const float*)d_in[13];
    const float* Wih_b  = (const float*)d_in[14];
    const float* Whh_b  = (const float*)d_in[15];
    const float* bih_b  = (const float*)d_in[16];
    const float* bhh_b  = (const float*)d_in[17];
    float* out = (float*)d_out;

    k_zero<<<(KSNAP * NNODE + 255) / 256, 256>>>();
    k_count<<<(KSNAP * EPTOT + 255) / 256, 256>>>(ei);
    k_scan<<<KSNAP, 1024>>>();
    k_scatter<<<(KSNAP * EPTOT + 255) / 256, 256>>>(ei);

    k_prep<<<1, 256>>>(W1, a_src1, a_dst1);

    dim3 gagg(NNODE / 8, KSNAP);
    k_agg1<<<gagg, 256>>>(xs);

    k_gemm<<<dim3(NTOT / 128, 2), 256>>>(W2, W1, b1, a_src2, a_dst2);
    k_agg2<<<gagg, 256>>>(b2);

    k_whhT<<<(2 * 128 * 1024 + 255) / 256, 256>>>(Whh_f, Whh_b);
    k_xw<<<2048, 256>>>(Wih_f, Wih_b);
    k_lstm<<<8, 1024>>>(bih_f, bhh_f, bih_b, bhh_b, out);
}

// round 8
// speedup vs baseline: 12.9738x; 1.1877x over previous
#include <cuda_runtime.h>
#include <cuda_bf16.h>
#include <cstdint>

// ---------------- problem constants ----------------
#define KSNAP 8
#define NNODE 10000
#define NEDGE 160000
#define EPTOT (NEDGE + NNODE)   // edges + self loops = 170000
#define HEADS 8
#define D2 256
#define LH 256
#define NEG 0.2f
#define NTOT (KSNAP * NNODE)    // 80000

// ---------------- static scratch ----------------
static __device__ unsigned int g_featb[NTOT * 128];    // h_lin bf16x2 packed
static __device__ float g_t   [NTOT * HEADS];          // layer-1 aggregated scalars per head
static __device__ float g_ssrc[NTOT * HEADS];
static __device__ float g_sdst[NTOT * HEADS];
static __device__ float g_q   [2 * HEADS];
static __device__ float g_theta[HEADS * 32];           // sorted knots per head
static __device__ int   g_perm [HEADS * 32];           // sorted order -> original k
static __device__ float g_tab  [HEADS * 33 * 2 * 256]; // [h][interval][S/I][j]
static __device__ int   g_deg [KSNAP * NNODE];
static __device__ int   g_off [KSNAP * (NNODE + 1)];
static __device__ int   g_pos [KSNAP * NNODE];
static __device__ int   g_adj [KSNAP * EPTOT];
static __device__ float g_emb [KSNAP * D2];
static __device__ float g_xw  [2 * KSNAP * 4 * LH];
static __device__ float2 g_whhT2[2 * 128 * 1024];

// ---------------- helpers ----------------
__device__ __forceinline__ float warp_sum(float v) {
#pragma unroll
    for (int o = 16; o; o >>= 1) v += __shfl_xor_sync(0xffffffffu, v, o);
    return v;
}
__device__ __forceinline__ float warp_max(float v) {
#pragma unroll
    for (int o = 16; o; o >>= 1) v = fmaxf(v, __shfl_xor_sync(0xffffffffu, v, o));
    return v;
}
__device__ __forceinline__ float warp_min(float v) {
#pragma unroll
    for (int o = 16; o; o >>= 1) v = fminf(v, __shfl_xor_sync(0xffffffffu, v, o));
    return v;
}
#define FMA2(d, a, b) asm("fma.rn.f32x2 %0, %1, %2, %0;" : "+l"(d) : "l"(a), "l"(b))
__device__ __forceinline__ void unpack2(unsigned long long v, float& lo, float& hi) {
    lo = __uint_as_float((unsigned int)(v & 0xffffffffull));
    hi = __uint_as_float((unsigned int)(v >> 32));
}
__device__ __forceinline__ float lky(float e) { return (e >= 0.f) ? e : NEG * e; }
__device__ __forceinline__ uint32_t pack_bf16x2(float a, float b) {
    __nv_bfloat162 p = __float22bfloat162_rn(make_float2(a, b));
    return *(uint32_t*)&p;
}
__device__ __forceinline__ uint32_t smem_u32(const void* p) {
    uint32_t a;
    asm("{ .reg .u64 t; cvta.to.shared.u64 t, %1; cvt.u32.u64 %0, t; }" : "=r"(a) : "l"(p));
    return a;
}
__device__ __forceinline__ uint32_t cluster_rank() {
    uint32_t r;
    asm("mov.u32 %0, %%cluster_ctarank;" : "=r"(r));
    return r;
}
__device__ __forceinline__ float dsmem_ld(uint32_t addr, uint32_t rank) {
    uint32_t ra; float v;
    asm("mapa.shared::cluster.u32 %0, %1, %2;" : "=r"(ra) : "r"(addr), "r"(rank));
    asm volatile("ld.shared::cluster.f32 %0, [%1];" : "=f"(v) : "r"(ra));
    return v;
}
#define CLUSTER_SYNC() do {                                            \
    asm volatile("barrier.cluster.arrive.aligned;" ::: "memory");      \
    asm volatile("barrier.cluster.wait.aligned;" ::: "memory");        \
} while (0)

// ---------------- CSR build ----------------
__global__ void k_zero() {
    int i = blockIdx.x * blockDim.x + threadIdx.x;
    if (i < KSNAP * NNODE) g_deg[i] = 0;
    if (i < KSNAP * D2)    g_emb[i] = 0.f;
}

__global__ void k_count(const int* __restrict__ ei) {
    int idx = blockIdx.x * blockDim.x + threadIdx.x;
    if (idx >= KSNAP * EPTOT) return;
    int k = idx / EPTOT, e = idx % EPTOT;
    int dst = (e < NEDGE) ? ei[(k * 2 + 1) * NEDGE + e] : (e - NEDGE);
    atomicAdd(&g_deg[k * NNODE + dst], 1);
}

__global__ void k_scan() {
    __shared__ int part[1024];
    int k = blockIdx.x, t = threadIdx.x;
    int base = t * 10;
    int loc[10];
    int s = 0;
#pragma unroll
    for (int i = 0; i < 10; i++) {
        int n = base + i;
        int v = (n < NNODE) ? g_deg[k * NNODE + n] : 0;
        loc[i] = s; s += v;
    }
    part[t] = s;
    __syncthreads();
    for (int ofs = 1; ofs < 1024; ofs <<= 1) {
        int v = (t >= ofs) ? part[t - ofs] : 0;
        __syncthreads();
        part[t] += v;
        __syncthreads();
    }
    int pre = (t == 0) ? 0 : part[t - 1];
#pragma unroll
    for (int i = 0; i < 10; i++) {
        int n = base + i;
        if (n < NNODE) {
            int o = pre + loc[i];
            g_off[k * (NNODE + 1) + n] = o;
            g_pos[k * NNODE + n]       = o;
        }
    }
    if (t == 1023) g_off[k * (NNODE + 1) + NNODE] = part[1023];
}

__global__ void k_scatter(const int* __restrict__ ei) {
    int idx = blockIdx.x * blockDim.x + threadIdx.x;
    if (idx >= KSNAP * EPTOT) return;
    int k = idx / EPTOT, e = idx % EPTOT;
    int src, dst;
    if (e < NEDGE) {
        src = ei[(k * 2 + 0) * NEDGE + e];
        dst = ei[(k * 2 + 1) * NEDGE + e];
    } else {
        src = e - NEDGE;
        dst = e - NEDGE;
    }
    int slot = atomicAdd(&g_pos[k * NNODE + dst], 1);
    g_adj[k * EPTOT + slot] = src;
}

// ---------------- prep: q vectors + per-head knot sort ----------------
__global__ void k_prep(const float* __restrict__ W1, const float* __restrict__ as1,
                       const float* __restrict__ ad1, const float* __restrict__ b1) {
    int c = threadIdx.x;
    int h = c >> 5, k = c & 31;
    float w = W1[c];
    float vs = warp_sum(w * as1[c]);
    float vd = warp_sum(w * ad1[c]);
    if (k == 0) {
        g_q[h] = vs;
        g_q[8 + h] = vd;
    }
    // knot: activation boundary of relu(W1[c]*s + b1[c])
    float b = b1[c];
    float th = (w != 0.f) ? (-b / w) : 1e30f;   // w==0: constant term, never flips
    unsigned rank = 0;
#pragma unroll
    for (int j = 0; j < 32; j++) {
        float tj = __shfl_sync(0xffffffffu, th, j);
        rank += (tj < th) || (tj == th && j < k);
    }
    g_theta[h * 32 + rank] = th;
    g_perm[h * 32 + rank] = k;
}

// ---------------- prep: PWL interval table (slope/intercept prefix sweep) ----------------
__global__ void k_sweep(const float* __restrict__ W1, const float* __restrict__ b1,
                        const float* __restrict__ W2) {
    int h = blockIdx.x, j = threadIdx.x;
    float slope = 0.f, intr = 0.f;
    // base interval r=0 (s below all knots): active = {w<0} ∪ {w==0 && b>0}
    for (int k = 0; k < 32; k++) {
        int g = h * 32 + k;
        float w = W1[g], b = b1[g], w2 = W2[g * 256 + j];
        if (w < 0.f)                  { slope = fmaf(w, w2, slope); intr = fmaf(b, w2, intr); }
        else if (w == 0.f && b > 0.f) { intr = fmaf(b, w2, intr); }
    }
    g_tab[((h * 33 + 0) * 2 + 0) * 256 + j] = slope;
    g_tab[((h * 33 + 0) * 2 + 1) * 256 + j] = intr;
    for (int r = 1; r <= 32; r++) {
        int k = g_perm[h * 32 + r - 1];
        int g = h * 32 + k;
        float w = W1[g], b = b1[g], w2 = W2[g * 256 + j];
        if (w > 0.f)      { slope = fmaf(w, w2, slope);  intr = fmaf(b, w2, intr); }
        else if (w < 0.f) { slope = fmaf(-w, w2, slope); intr = fmaf(-b, w2, intr); }
        g_tab[((h * 33 + r) * 2 + 0) * 256 + j] = slope;
        g_tab[((h * 33 + r) * 2 + 1) * 256 + j] = intr;
    }
}

// ---------------- layer-1 GAT, scalar, exact-max ----------------
__global__ __launch_bounds__(256) void k_agg1(const float* __restrict__ xs) {
    int k = blockIdx.y;
    int n = blockIdx.x * 8 + (threadIdx.x >> 5);
    int lane = threadIdx.x & 31;
    long base = (long)k * NNODE;
    int o0 = g_off[k * (NNODE + 1) + n];
    int o1 = g_off[k * (NNODE + 1) + n + 1];
    const int* adj = g_adj + (long)k * EPTOT;

    float qs[HEADS], dterm[HEADS];
    float xd = xs[base + n];
#pragma unroll
    for (int i = 0; i < HEADS; i++) { qs[i] = g_q[i]; dterm[i] = xd * g_q[8 + i]; }

    float xmx = -1e30f, xmn = 1e30f;
    for (int j = o0 + lane; j < o1; j += 32) {
        float xv = xs[base + adj[j]];
        xmx = fmaxf(xmx, xv); xmn = fminf(xmn, xv);
    }
    xmx = warp_max(xmx); xmn = warp_min(xmn);
    float m[HEADS];
#pragma unroll
    for (int i = 0; i < HEADS; i++)
        m[i] = lky(fmaf(qs[i], (qs[i] >= 0.f) ? xmx : xmn, dterm[i]));

    float dsum[HEADS], tt[HEADS];
#pragma unroll
    for (int i = 0; i < HEADS; i++) { dsum[i] = 0.f; tt[i] = 0.f; }
    for (int j = o0 + lane; j < o1; j += 32) {
        float xv = xs[base + adj[j]];
#pragma unroll
        for (int i = 0; i < HEADS; i++) {
            float e = lky(fmaf(xv, qs[i], dterm[i]));
            float ex = __expf(e - m[i]);
            dsum[i] += ex;
            tt[i] = fmaf(ex, xv, tt[i]);
        }
    }
#pragma unroll
    for (int i = 0; i < HEADS; i++) {
        float ds = warp_sum(dsum[i]);
        float ts = warp_sum(tt[i]);
        if (lane == 0) g_t[(base + n) * HEADS + i] = ts / (ds + 1e-16f);
    }
}

// ---------------- PWL "GEMM": h_lin[n,j] = sum_h S[h][r_h][j]*t_h + I[h][r_h][j] ----------------
// warp per node; lane owns channels lane*8..+7
__global__ __launch_bounds__(256) void k_pwl(const float* __restrict__ as2,
                                             const float* __restrict__ ad2) {
    int widx = threadIdx.x >> 5;
    long n = (long)blockIdx.x * 8 + widx;
    int lane = threadIdx.x & 31;
    int j0 = lane * 8;

    float tv = 0.f;
    int r = 0;
    if (lane < 8) {
        tv = g_t[n * 8 + lane];
        const float* th = &g_theta[lane * 32];
#pragma unroll
        for (int k = 0; k < 32; k++) r += (th[k] < tv);
    }

    float acc[8];
#pragma unroll
    for (int q = 0; q < 8; q++) acc[q] = 0.f;

#pragma unroll
    for (int h = 0; h < 8; h++) {
        float th = __shfl_sync(0xffffffffu, tv, h);
        int rh = __shfl_sync(0xffffffffu, r, h);
        const float* S = &g_tab[(long)((h * 33 + rh) * 2) * 256 + j0];
        float4 s0 = *(const float4*)S;
        float4 s1 = *(const float4*)(S + 4);
        float4 i0 = *(const float4*)(S + 256);
        float4 i1 = *(const float4*)(S + 260);
        acc[0] = fmaf(s0.x, th, acc[0] + i0.x);
        acc[1] = fmaf(s0.y, th, acc[1] + i0.y);
        acc[2] = fmaf(s0.z, th, acc[2] + i0.z);
        acc[3] = fmaf(s0.w, th, acc[3] + i0.w);
        acc[4] = fmaf(s1.x, th, acc[4] + i1.x);
        acc[5] = fmaf(s1.y, th, acc[5] + i1.y);
        acc[6] = fmaf(s1.z, th, acc[6] + i1.z);
        acc[7] = fmaf(s1.w, th, acc[7] + i1.w);
    }

    // store features as bf16x2
    uint4 pkd = make_uint4(pack_bf16x2(acc[0], acc[1]), pack_bf16x2(acc[2], acc[3]),
                           pack_bf16x2(acc[4], acc[5]), pack_bf16x2(acc[6], acc[7]));
    *(uint4*)&g_featb[n * 128 + lane * 4] = pkd;

    // s-vectors: 4-lane quad owns head (lane>>2)
    float ss = 0.f, sd = 0.f;
#pragma unroll
    for (int q = 0; q < 8; q++) {
        ss = fmaf(acc[q], as2[j0 + q], ss);
        sd = fmaf(acc[q], ad2[j0 + q], sd);
    }
    ss += __shfl_xor_sync(0xffffffffu, ss, 1);
    ss += __shfl_xor_sync(0xffffffffu, ss, 2);
    sd += __shfl_xor_sync(0xffffffffu, sd, 1);
    sd += __shfl_xor_sync(0xffffffffu, sd, 2);
    if ((lane & 3) == 0) {
        g_ssrc[n * HEADS + (lane >> 2)] = ss;
        g_sdst[n * HEADS + (lane >> 2)] = sd;
    }
}

// ---------------- layer-2 GAT aggregation + CTA-pooled mean ----------------
__global__ __launch_bounds__(256) void k_agg2(const float* __restrict__ bias) {
    __shared__ float s_m[8][8];
    __shared__ float pool[8][256];
    int k = blockIdx.y;
    int w = threadIdx.x >> 5;
    int n = blockIdx.x * 8 + w;
    int lane = threadIdx.x & 31;
    long base = (long)k * NNODE;
    int o0 = g_off[k * (NNODE + 1) + n];
    int o1 = g_off[k * (NNODE + 1) + n + 1];
    const int* adj = g_adj + (long)k * EPTOT;

    float sd[HEADS];
    {
        float4 d0 = *(const float4*)&g_sdst[(base + n) * HEADS];
        float4 d1 = *(const float4*)&g_sdst[(base + n) * HEADS + 4];
        sd[0] = d0.x; sd[1] = d0.y; sd[2] = d0.z; sd[3] = d0.w;
        sd[4] = d1.x; sd[5] = d1.y; sd[6] = d1.z; sd[7] = d1.w;
    }

    float mx[HEADS];
#pragma unroll
    for (int i = 0; i < HEADS; i++) mx[i] = -1e30f;
    for (int j = o0 + lane; j < o1; j += 32) {
        const float4* sp = (const float4*)&g_ssrc[((long)base + adj[j]) * HEADS];
        float4 s0 = sp[0], s1 = sp[1];
        mx[0] = fmaxf(mx[0], s0.x); mx[1] = fmaxf(mx[1], s0.y);
        mx[2] = fmaxf(mx[2], s0.z); mx[3] = fmaxf(mx[3], s0.w);
        mx[4] = fmaxf(mx[4], s1.x); mx[5] = fmaxf(mx[5], s1.y);
        mx[6] = fmaxf(mx[6], s1.z); mx[7] = fmaxf(mx[7], s1.w);
    }
#pragma unroll
    for (int i = 0; i < HEADS; i++) mx[i] = warp_max(mx[i]);
    if (lane == 0) {
#pragma unroll
        for (int i = 0; i < HEADS; i++) s_m[w][i] = lky(mx[i] + sd[i]);
    }
    __syncwarp();

    int hl = lane >> 2;
    float m_l = s_m[w][hl];
    float sd_l = sd[hl];

    float dsum = 0.f;
    float a0 = 0.f, a1 = 0.f, a2 = 0.f, a3 = 0.f, a4 = 0.f, a5 = 0.f, a6 = 0.f, a7 = 0.f;
    for (int j = o0; j < o1; j++) {
        long s = adj[j];
        float e = lky(g_ssrc[(base + s) * HEADS + hl] + sd_l);
        float al = __expf(e - m_l);
        dsum += al;
        uint4 fv = *(const uint4*)&g_featb[(base + s) * 128 + lane * 4];
        float2 f0 = __bfloat1622float2(*(__nv_bfloat162*)&fv.x);
        float2 f1 = __bfloat1622float2(*(__nv_bfloat162*)&fv.y);
        float2 f2 = __bfloat1622float2(*(__nv_bfloat162*)&fv.z);
        float2 f3 = __bfloat1622float2(*(__nv_bfloat162*)&fv.w);
        a0 = fmaf(f0.x, al, a0); a1 = fmaf(f0.y, al, a1);
        a2 = fmaf(f1.x, al, a2); a3 = fmaf(f1.y, al, a3);
        a4 = fmaf(f2.x, al, a4); a5 = fmaf(f2.y, al, a5);
        a6 = fmaf(f3.x, al, a6); a7 = fmaf(f3.y, al, a7);
    }
    float inv = 1.f / (dsum + 1e-16f);
    float4 b0 = *(const float4*)&bias[lane * 8];
    float4 b1v = *(const float4*)&bias[lane * 8 + 4];
    float* pw = &pool[w][lane * 8];
    pw[0] = fmaxf(fmaf(a0, inv, b0.x), 0.f);
    pw[1] = fmaxf(fmaf(a1, inv, b0.y), 0.f);
    pw[2] = fmaxf(fmaf(a2, inv, b0.z), 0.f);
    pw[3] = fmaxf(fmaf(a3, inv, b0.w), 0.f);
    pw[4] = fmaxf(fmaf(a4, inv, b1v.x), 0.f);
    pw[5] = fmaxf(fmaf(a5, inv, b1v.y), 0.f);
    pw[6] = fmaxf(fmaf(a6, inv, b1v.z), 0.f);
    pw[7] = fmaxf(fmaf(a7, inv, b1v.w), 0.f);
    __syncthreads();

    int c = threadIdx.x;
    float s8 = pool[0][c] + pool[1][c] + pool[2][c] + pool[3][c]
             + pool[4][c] + pool[5][c] + pool[6][c] + pool[7][c];
    atomicAdd(&g_emb[k * D2 + c], s8 * (1.0f / NNODE));
}

// ---------------- LSTM input projections ----------------
__global__ void k_xw(const float* __restrict__ Wih_f, const float* __restrict__ Wih_b) {
    int gid = blockIdx.x * 8 + (threadIdx.x >> 5);
    int lane = threadIdx.x & 31;
    int d = gid >> 13;
    int rem = gid & 8191;
    int k = rem >> 10;
    int g = rem & 1023;
    const float* Wih = d ? Wih_b : Wih_f;
    float s = 0.f;
    for (int j = lane; j < D2; j += 32)
        s += Wih[g * D2 + j] * g_emb[k * D2 + j];
    s = warp_sum(s);
    if (lane == 0) g_xw[gid] = s;
}

__global__ void k_whhT(const float* __restrict__ Whh_f, const float* __restrict__ Whh_b) {
    int idx = blockIdx.x * blockDim.x + threadIdx.x;
    if (idx >= 2 * 128 * 1024) return;
    int d = idx >> 17;
    int r = idx & ((1 << 17) - 1);
    int j2 = r >> 10;
    int t = r & 1023;
    const float* W = d ? Whh_b : Whh_f;
    g_whhT2[(((long)d * 128 + j2) << 10) + t] = make_float2(W[t * 256 + 2 * j2], W[t * 256 + 2 * j2 + 1]);
}

// ---------------- bidirectional LSTM: 4-CTA cluster per direction, split-j + DSMEM ----------------
__global__ __launch_bounds__(1024) __cluster_dims__(4, 1, 1)
void k_lstm(const float* __restrict__ bih_f, const float* __restrict__ bhh_f,
            const float* __restrict__ bih_b, const float* __restrict__ bhh_b,
            float* __restrict__ out) {
    int d = blockIdx.x >> 2;
    uint32_t rank = cluster_rank();
    int t = threadIdx.x;

    __shared__ __align__(16) float ps[2][1024];
    __shared__ __align__(16) float hloc[64];
    __shared__ float g4[256];
    __shared__ float xw_s[KSNAP][256];

    const float* bih = d ? bih_b : bih_f;
    const float* bhh = d ? bhh_b : bhh_f;

    int gidx = (t >> 6) * 256 + rank * 64 + (t & 63);
    if (t < 256) {
        float bsum = bih[gidx] + bhh[gidx];
#pragma unroll
        for (int k = 0; k < KSNAP; k++) {
            int kk = d ? (KSNAP - 1 - k) : k;
            xw_s[k][t] = g_xw[((long)d * KSNAP + kk) * 1024 + gidx] + bsum;
        }
    }
    if (t < 64) hloc[t] = 0.f;
    float cstate = 0.f;

    const unsigned long long* WT =
        (const unsigned long long*)(g_whhT2 + (long)d * 128 * 1024) + (long)(rank * 32) * 1024 + t;
    const unsigned long long* hp = (const unsigned long long*)hloc;
    uint32_t ps_base = smem_u32(&ps[0][0]);

    __syncthreads();
    CLUSTER_SYNC();

    int b = 0;
    for (int step = 0; step < KSNAP; step++) {
        unsigned long long acc2 = 0ull;
#pragma unroll
        for (int jj = 0; jj < 32; jj++)
            FMA2(acc2, WT[(long)jj * 1024], hp[jj]);
        float lo, hi;
        unpack2(acc2, lo, hi);
        ps[b][t] = lo + hi;
        __syncthreads();
        CLUSTER_SYNC();

        if (t < 256) {
            uint32_t pa = ps_base + (b * 1024 + gidx) * 4;
            float v = xw_s[step][t];
            v += dsmem_ld(pa, 0);
            v += dsmem_ld(pa, 1);
            v += dsmem_ld(pa, 2);
            v += dsmem_ld(pa, 3);
            g4[t] = v;
        }
        __syncthreads();

        if (t < 64) {
            float ig = 1.f / (1.f + expf(-g4[t]));
            float fg = 1.f / (1.f + expf(-g4[64 + t]));
            float gg = tanhf(g4[128 + t]);
            float og = 1.f / (1.f + expf(-g4[192 + t]));
            cstate = fg * cstate + ig * gg;
            hloc[t] = og * tanhf(cstate);
        }
        __syncthreads();
        b ^= 1;
    }

    if (t < 64) out[d * LH + rank * 64 + t] = hloc[t];
    CLUSTER_SYNC();
}

// ---------------- launch ----------------
extern "C" void kernel_launch(void* const* d_in, const int* in_sizes, int n_in,
                              void* d_out, int out_size) {
    const float* xs     = (const float*)d_in[0];
    const int*   ei     = (const int*)  d_in[1];
    const float* W1     = (const float*)d_in[2];
    const float* a_src1 = (const float*)d_in[3];
    const float* a_dst1 = (const float*)d_in[4];
    const float* b1     = (const float*)d_in[5];
    const float* W2     = (const float*)d_in[6];
    const float* a_src2 = (const float*)d_in[7];
    const float* a_dst2 = (const float*)d_in[8];
    const float* b2     = (const float*)d_in[9];
    const float* Wih_f  = (const float*)d_in[10];
    const float* Whh_f  = (const float*)d_in[11];
    const float* bih_f  = (const float*)d_in[12];
    const float* bhh_f  = (const float*)d_in[13];
    const float* Wih_b  = (const float*)d_in[14];
    const float* Whh_b  = (const float*)d_in[15];
    const float* bih_b  = (const float*)d_in[16];
    const float* bhh_b  = (const float*)d_in[17];
    float* out = (float*)d_out;

    k_zero<<<(KSNAP * NNODE + 255) / 256, 256>>>();
    k_count<<<(KSNAP * EPTOT + 255) / 256, 256>>>(ei);
    k_scan<<<KSNAP, 1024>>>();
    k_scatter<<<(KSNAP * EPTOT + 255) / 256, 256>>>(ei);

    k_prep<<<1, 256>>>(W1, a_src1, a_dst1, b1);
    k_sweep<<<HEADS, 256>>>(W1, b1, W2);

    dim3 gagg(NNODE / 8, KSNAP);
    k_agg1<<<gagg, 256>>>(xs);

    k_pwl<<<NTOT / 8, 256>>>(a_src2, a_dst2);
    k_agg2<<<gagg, 256>>>(b2);

    k_whhT<<<(2 * 128 * 1024 + 255) / 256, 256>>>(Whh_f, Whh_b);
    k_xw<<<2048, 256>>>(Wih_f, Wih_b);
    k_lstm<<<8, 1024>>>(bih_f, bhh_f, bih_b, bhh_b, out);
}